// round 1
// baseline (speedup 1.0000x reference)
#include <cuda_runtime.h>
#include <cstdint>

// ---------------- problem constants ----------------
#define C0   12
#define D0   240
#define H0   144
#define W0   240
#define HW0  (H0*W0)
#define VV   (D0*H0*W0)          // 8,294,400 voxels
#define PIX  (480*640)           // 307,200 pixels

#define D1 120
#define H1 72
#define W1 120
#define N1 (D1*H1*W1)            // 1,036,800

#define D2 60
#define H2 36
#define W2 60
#define N2 (D2*H2*W2)            // 129,600

#define NEG_INF (__int_as_float(0xff800000))

// ---------------- scratch (static device memory; no allocation) -------------
__device__ float g_segres[(size_t)C0*VV];   // scattered features (zero-init each run)
__device__ float g_filled[(size_t)C0*VV];   // segres + pool*(segres==0)
__device__ int   g_winner[VV];              // last-pixel-wins selection
__device__ float g_ds1[(size_t)16*N1];
__device__ float g_t0[(size_t)4*N1];
__device__ float g_t1[(size_t)4*N1];
__device__ float g_t2[(size_t)4*N1];
__device__ float g_t3[(size_t)4*N1];
__device__ float g_bn1[(size_t)16*N1];
__device__ float g_ds2[(size_t)32*N2];
__device__ float g_u0[(size_t)8*N2];
__device__ float g_u1[(size_t)8*N2];
__device__ float g_u2[(size_t)8*N2];
__device__ float g_u3[(size_t)8*N2];

// ---------------- kernels ----------------

// Zero segres (float4) and set winner to -1 (int4).
__global__ void k_init() {
    int i = blockIdx.x * blockDim.x + threadIdx.x;
    const int n4 = C0*VV/4;                  // 24,883,200
    if (i < n4) ((float4*)g_segres)[i] = make_float4(0.f,0.f,0.f,0.f);
    if (i < VV/4) ((int4*)g_winner)[i] = make_int4(-1,-1,-1,-1);
}

// Pass 1: pick the winning (largest) pixel index per voxel — matches XLA CPU
// sequential scatter where the last duplicate update wins.
__global__ void k_winner(const int* __restrict__ depth) {
    int p = blockIdx.x * blockDim.x + threadIdx.x;
    if (p >= PIX) return;
    int d = depth[p];
    if (d > 0) atomicMax(&g_winner[d], p);
}

// Pass 2: scatter the 12-channel feature vector of the winning pixel.
__global__ void k_scatter(const float* __restrict__ feat, const int* __restrict__ depth) {
    int p = blockIdx.x * blockDim.x + threadIdx.x;
    if (p >= PIX) return;
    int d = depth[p];
    if (d > 0 && g_winner[d] == p) {
        #pragma unroll
        for (int c = 0; c < C0; c++)
            g_segres[(size_t)c*VV + d] = feat[(size_t)c*PIX + p];
    }
}

// AvgPool3d(k=3,p=1,s=1, count_include_pad) fill:
//   filled = (segres==0) ? window_sum/27 : segres
// One thread per (c,y,x), marching z with sliding plane sums (9 loads/step).
__global__ void k_fill() {
    int gid = blockIdx.x * blockDim.x + threadIdx.x;
    if (gid >= C0*H0*W0) return;
    int x = gid % W0;
    int y = (gid / W0) % H0;
    int c = gid / (H0*W0);
    const float* base = g_segres + (size_t)c*VV;
    float*       outb = g_filled + (size_t)c*VV;

    auto psum = [&](int z, float& ctr) -> float {
        const float* pl = base + (size_t)z*HW0;
        float s = 0.f; ctr = 0.f;
        #pragma unroll
        for (int dy = -1; dy <= 1; dy++) {
            int yy = y + dy;
            if ((unsigned)yy >= (unsigned)H0) continue;
            const float* row = pl + yy*W0;
            #pragma unroll
            for (int dx = -1; dx <= 1; dx++) {
                int xx = x + dx;
                if ((unsigned)xx >= (unsigned)W0) continue;
                float v = row[xx];
                s += v;
                if (dy == 0 && dx == 0) ctr = v;
            }
        }
        return s;
    };

    float ctr_cur, ctr_next;
    float s_prev = 0.f;
    float s_cur  = psum(0, ctr_cur);
    for (int z = 0; z < D0; z++) {
        float s_next = 0.f; ctr_next = 0.f;
        if (z + 1 < D0) s_next = psum(z + 1, ctr_next);
        float sum = s_prev + s_cur + s_next;
        float o = (ctr_cur == 0.f) ? sum * (1.f/27.f) : ctr_cur;
        outb[(size_t)z*HW0 + y*W0 + x] = o;
        s_prev = s_cur; s_cur = s_next; ctr_cur = ctr_next;
    }
}

// Fused downsample block: conv(CIN->CC, k3 s2 p1) || maxpool(2,2,2), concat, relu.
// One thread per output voxel; pool taps harvested from the conv tap loads.
template<int CIN, int CC>
__global__ void k_down(const float* __restrict__ in, const float* __restrict__ w,
                       float* __restrict__ out,
                       int Dd, int Hh, int Ww, int Hin, int Win) {
    extern __shared__ float sw[];
    const int NW = CC*CIN*27;
    for (int i = threadIdx.x; i < NW; i += blockDim.x) sw[i] = w[i];
    __syncthreads();

    int N = Dd*Hh*Ww;
    int gid = blockIdx.x * blockDim.x + threadIdx.x;
    if (gid >= N) return;
    int x = gid % Ww;
    int y = (gid / Ww) % Hh;
    int z = gid / (Ww*Hh);
    size_t HWin = (size_t)Hin*Win;
    size_t Vin  = (size_t)(2*Dd)*HWin;

    float acc[CC];
    #pragma unroll
    for (int o = 0; o < CC; o++) acc[o] = 0.f;

    for (int i = 0; i < CIN; i++) {
        const float* inp = in + (size_t)i*Vin;
        float m = NEG_INF;
        #pragma unroll
        for (int dz = 0; dz < 3; dz++) {
            int iz = 2*z - 1 + dz;
            if (iz < 0) continue;                 // upper bound never exceeded
            #pragma unroll
            for (int dy = 0; dy < 3; dy++) {
                int iy = 2*y - 1 + dy;
                if (iy < 0) continue;
                #pragma unroll
                for (int dx = 0; dx < 3; dx++) {
                    int ix = 2*x - 1 + dx;
                    if (ix < 0) continue;
                    float v = inp[(size_t)iz*HWin + (size_t)iy*Win + ix];
                    int widx = i*27 + dz*9 + dy*3 + dx;
                    #pragma unroll
                    for (int o = 0; o < CC; o++)
                        acc[o] = fmaf(sw[o*CIN*27 + widx], v, acc[o]);
                    if (dz > 0 && dy > 0 && dx > 0) m = fmaxf(m, v);  // 2x2x2 pool window
                }
            }
        }
        out[(size_t)(CC + i)*N + gid] = fmaxf(m, 0.f);
    }
    #pragma unroll
    for (int o = 0; o < CC; o++)
        out[(size_t)o*N + gid] = fmaxf(acc[o], 0.f);
}

// Generic bottleneck conv: out = relu(conv(in) [+bias] [+add1] [+add2]).
// Weights OIDHW in smem, per-voxel thread.
template<int CIN, int COUT, int KD, int KH, int KW>
__global__ void k_conv(const float* __restrict__ in, const float* __restrict__ w,
                       const float* __restrict__ bias,
                       const float* __restrict__ add1, const float* __restrict__ add2,
                       float* __restrict__ out,
                       int Dd, int Hh, int Ww) {
    constexpr int KSZ = KD*KH*KW;
    __shared__ float sw[COUT*CIN*KSZ];
    __shared__ float sb[COUT];
    for (int i = threadIdx.x; i < COUT*CIN*KSZ; i += blockDim.x) sw[i] = w[i];
    if (threadIdx.x < COUT) sb[threadIdx.x] = bias ? bias[threadIdx.x] : 0.f;
    __syncthreads();

    int N = Dd*Hh*Ww;
    int gid = blockIdx.x * blockDim.x + threadIdx.x;
    if (gid >= N) return;
    int x = gid % Ww;
    int y = (gid / Ww) % Hh;
    int z = gid / (Ww*Hh);

    float acc[COUT];
    #pragma unroll
    for (int o = 0; o < COUT; o++) acc[o] = sb[o];

    for (int i = 0; i < CIN; i++) {
        const float* base = in + (size_t)i*N;
        #pragma unroll
        for (int dz = 0; dz < KD; dz++) {
            int iz = z - KD/2 + dz;
            if ((unsigned)iz >= (unsigned)Dd) continue;
            #pragma unroll
            for (int dy = 0; dy < KH; dy++) {
                int iy = y - KH/2 + dy;
                if ((unsigned)iy >= (unsigned)Hh) continue;
                #pragma unroll
                for (int dx = 0; dx < KW; dx++) {
                    int ix = x - KW/2 + dx;
                    if ((unsigned)ix >= (unsigned)Ww) continue;
                    float v = base[((size_t)iz*Hh + iy)*Ww + ix];
                    int widx = (i*KD + dz)*KH*KW + dy*KW + dx;
                    #pragma unroll
                    for (int o = 0; o < COUT; o++)
                        acc[o] = fmaf(sw[o*CIN*KSZ + widx], v, acc[o]);
                }
            }
        }
    }
    #pragma unroll
    for (int o = 0; o < COUT; o++) {
        float r = acc[o];
        if (add1) r += add1[(size_t)o*N + gid];
        if (add2) r += add2[(size_t)o*N + gid];
        out[(size_t)o*N + gid] = fmaxf(r, 0.f);
    }
}

// ---------------- launch ----------------
static inline int gridFor(long n, int b) { return (int)((n + b - 1) / b); }

extern "C" void kernel_launch(void* const* d_in, const int* in_sizes, int n_in,
                              void* d_out, int out_size) {
    const float* feat    = (const float*)d_in[0];
    const int*   depth   = (const int*)  d_in[1];
    const float* w_ds1   = (const float*)d_in[2];
    const float* b1_win  = (const float*)d_in[3];
    const float* b1_w133 = (const float*)d_in[4];
    const float* b1_b133 = (const float*)d_in[5];
    const float* b1_w331 = (const float*)d_in[6];
    const float* b1_b331 = (const float*)d_in[7];
    const float* b1_w313 = (const float*)d_in[8];
    const float* b1_b313 = (const float*)d_in[9];
    const float* b1_wout = (const float*)d_in[10];
    const float* w_ds2   = (const float*)d_in[11];
    const float* b2_win  = (const float*)d_in[12];
    const float* b2_w133 = (const float*)d_in[13];
    const float* b2_b133 = (const float*)d_in[14];
    const float* b2_w331 = (const float*)d_in[15];
    const float* b2_b331 = (const float*)d_in[16];
    const float* b2_w313 = (const float*)d_in[17];
    const float* b2_b313 = (const float*)d_in[18];
    const float* b2_wout = (const float*)d_in[19];
    float* out = (float*)d_out;

    void *p_filled_, *p_ds1_, *p_t0_, *p_t1_, *p_t2_, *p_t3_, *p_bn1_, *p_ds2_,
         *p_u0_, *p_u1_, *p_u2_, *p_u3_;
    cudaGetSymbolAddress(&p_filled_, g_filled);
    cudaGetSymbolAddress(&p_ds1_, g_ds1);
    cudaGetSymbolAddress(&p_t0_, g_t0);
    cudaGetSymbolAddress(&p_t1_, g_t1);
    cudaGetSymbolAddress(&p_t2_, g_t2);
    cudaGetSymbolAddress(&p_t3_, g_t3);
    cudaGetSymbolAddress(&p_bn1_, g_bn1);
    cudaGetSymbolAddress(&p_ds2_, g_ds2);
    cudaGetSymbolAddress(&p_u0_, g_u0);
    cudaGetSymbolAddress(&p_u1_, g_u1);
    cudaGetSymbolAddress(&p_u2_, g_u2);
    cudaGetSymbolAddress(&p_u3_, g_u3);
    float* p_filled = (float*)p_filled_;
    float* p_ds1 = (float*)p_ds1_;
    float* p_t0 = (float*)p_t0_; float* p_t1 = (float*)p_t1_;
    float* p_t2 = (float*)p_t2_; float* p_t3 = (float*)p_t3_;
    float* p_bn1 = (float*)p_bn1_;
    float* p_ds2 = (float*)p_ds2_;
    float* p_u0 = (float*)p_u0_; float* p_u1 = (float*)p_u1_;
    float* p_u2 = (float*)p_u2_; float* p_u3 = (float*)p_u3_;

    const int TB = 256;

    // scatter stage
    k_init   <<<gridFor((long)C0*VV/4, TB), TB>>>();
    k_winner <<<gridFor(PIX, TB), TB>>>(depth);
    k_scatter<<<gridFor(PIX, TB), TB>>>(feat, depth);

    // avgpool fill
    k_fill<<<gridFor((long)C0*H0*W0, TB), TB>>>();

    // downsample 1: 12ch@240x144x240 -> 16ch@120x72x120
    k_down<12,4><<<gridFor(N1, TB), TB, 4*12*27*sizeof(float)>>>(
        p_filled, w_ds1, p_ds1, D1, H1, W1, H0, W0);

    // bottleneck 1 (16 -> 4 -> ... -> 16, residual)
    k_conv<16,4,1,1,1><<<gridFor(N1, TB), TB>>>(p_ds1, b1_win,  nullptr, nullptr, nullptr, p_t0, D1, H1, W1);
    k_conv<4, 4,1,3,3><<<gridFor(N1, TB), TB>>>(p_t0,  b1_w133, b1_b133, nullptr, nullptr, p_t1, D1, H1, W1);
    k_conv<4, 4,3,3,1><<<gridFor(N1, TB), TB>>>(p_t1,  b1_w331, b1_b331, p_t1,    nullptr, p_t2, D1, H1, W1);
    k_conv<4, 4,3,1,3><<<gridFor(N1, TB), TB>>>(p_t2,  b1_w313, b1_b313, p_t2,    p_t1,    p_t3, D1, H1, W1);
    k_conv<4,16,1,1,1><<<gridFor(N1, TB), TB>>>(p_t3,  b1_wout, nullptr, p_ds1,   nullptr, p_bn1, D1, H1, W1);

    // downsample 2: 16ch@120x72x120 -> 32ch@60x36x60
    k_down<16,16><<<gridFor(N2, TB), TB, 16*16*27*sizeof(float)>>>(
        p_bn1, w_ds2, p_ds2, D2, H2, W2, H1, W1);

    // bottleneck 2 (32 -> 8 -> ... -> 32, residual), final write to d_out
    k_conv<32,8,1,1,1><<<gridFor(N2, TB), TB>>>(p_ds2, b2_win,  nullptr, nullptr, nullptr, p_u0, D2, H2, W2);
    k_conv<8, 8,1,3,3><<<gridFor(N2, TB), TB>>>(p_u0,  b2_w133, b2_b133, nullptr, nullptr, p_u1, D2, H2, W2);
    k_conv<8, 8,3,3,1><<<gridFor(N2, TB), TB>>>(p_u1,  b2_w331, b2_b331, p_u1,    nullptr, p_u2, D2, H2, W2);
    k_conv<8, 8,3,1,3><<<gridFor(N2, TB), TB>>>(p_u2,  b2_w313, b2_b313, p_u2,    p_u1,    p_u3, D2, H2, W2);
    k_conv<8,32,1,1,1><<<gridFor(N2, TB), TB>>>(p_u3,  b2_wout, nullptr, p_ds2,   nullptr, out,  D2, H2, W2);
}

// round 2
// speedup vs baseline: 1.7394x; 1.7394x over previous
#include <cuda_runtime.h>
#include <cstdint>

// ---------------- problem constants ----------------
#define C0   12
#define D0   240
#define H0   144
#define W0   240
#define HW0  (H0*W0)
#define VV   (D0*H0*W0)          // 8,294,400 voxels
#define PIX  (480*640)           // 307,200 pixels

#define D1 120
#define H1 72
#define W1 120
#define N1 (D1*H1*W1)            // 1,036,800

#define D2 60
#define H2 36
#define W2 60
#define N2 (D2*H2*W2)            // 129,600

#define ZCH 6                    // z-chunks in k_fill
#define ZL  (D0/ZCH)             // 40

#define NEG_INF (__int_as_float(0xff800000))

// ---------------- scratch (static device memory; no allocation) -------------
__device__ float g_segres[(size_t)C0*VV];   // scattered features (zero-init each run)
__device__ float g_filled[(size_t)C0*VV];   // segres + pool*(segres==0)
__device__ int   g_winner[VV];              // last-pixel-wins selection
__device__ float g_ds1[(size_t)16*N1];
__device__ float g_t0[(size_t)4*N1];
__device__ float g_t1[(size_t)4*N1];
__device__ float g_t2[(size_t)4*N1];
__device__ float g_t3[(size_t)4*N1];
__device__ float g_bn1[(size_t)16*N1];
__device__ float g_ds2[(size_t)32*N2];
__device__ float g_u0[(size_t)8*N2];
__device__ float g_u1[(size_t)8*N2];
__device__ float g_u2[(size_t)8*N2];
__device__ float g_u3[(size_t)8*N2];

// ---------------- kernels ----------------

// Zero segres (float4) and set winner to -1 (int4).
__global__ void k_init() {
    int i = blockIdx.x * blockDim.x + threadIdx.x;
    const int n4 = C0*VV/4;                  // 24,883,200
    if (i < n4) ((float4*)g_segres)[i] = make_float4(0.f,0.f,0.f,0.f);
    if (i < VV/4) ((int4*)g_winner)[i] = make_int4(-1,-1,-1,-1);
}

// Pass 1: pick the winning (largest) pixel index per voxel — matches XLA
// sequential scatter where the last duplicate update wins.
__global__ void k_winner(const int* __restrict__ depth) {
    int p = blockIdx.x * blockDim.x + threadIdx.x;
    if (p >= PIX) return;
    int d = depth[p];
    if (d > 0) atomicMax(&g_winner[d], p);
}

// Pass 2: scatter the 12-channel feature vector of the winning pixel.
__global__ void k_scatter(const float* __restrict__ feat, const int* __restrict__ depth) {
    int p = blockIdx.x * blockDim.x + threadIdx.x;
    if (p >= PIX) return;
    int d = depth[p];
    if (d > 0 && g_winner[d] == p) {
        #pragma unroll
        for (int c = 0; c < C0; c++)
            g_segres[(size_t)c*VV + d] = feat[(size_t)c*PIX + p];
    }
}

// AvgPool3d(k=3,p=1,s=1, count_include_pad) fill, vectorized:
//   filled = (segres==0) ? window_sum/27 : segres
// One thread per (c, y, x-quad, z-chunk); marches ZL planes with sliding
// plane sums. Per z-plane: 3 aligned float4 loads + up to 6 edge scalars.
__global__ void k_fill_v() {
    const int XQ = W0/4;   // 60
    int gid = blockIdx.x * blockDim.x + threadIdx.x;
    if (gid >= C0*H0*XQ*ZCH) return;
    int xq = gid % XQ;
    int y  = (gid / XQ) % H0;
    int zc = (gid / (XQ*H0)) % ZCH;
    int c  = gid / (XQ*H0*ZCH);
    int x0 = xq * 4;
    int z0 = zc * ZL;

    const float* base = g_segres + (size_t)c*VV;
    float*       outb = g_filled + (size_t)c*VV;

    // hoisted (z-invariant) row validity + offsets
    bool ym0 = (y > 0), ym2 = (y < H0-1);
    int ro0 = (y-1)*W0 + x0;
    int ro1 =  y   *W0 + x0;
    int ro2 = (y+1)*W0 + x0;
    bool lx = (x0 > 0), rx = (x0 + 4 < W0);

    auto plane = [&](int z, float4& s, float4& ctr) {
        const float* pl = base + (size_t)z*HW0;
        s = make_float4(0.f,0.f,0.f,0.f);
        #pragma unroll
        for (int dy = 0; dy < 3; dy++) {
            if (dy == 0 && !ym0) continue;
            if (dy == 2 && !ym2) continue;
            const float* r = pl + (dy == 0 ? ro0 : (dy == 1 ? ro1 : ro2));
            float4 m = *(const float4*)r;
            float a = lx ? r[-1] : 0.f;
            float b = rx ? r[4]  : 0.f;
            s.x += a   + m.x + m.y;
            s.y += m.x + m.y + m.z;
            s.z += m.y + m.z + m.w;
            s.w += m.z + m.w + b;
            if (dy == 1) ctr = m;
        }
    };

    float4 sp, sc, sn, cc_, cn, dum;
    const float4 z4 = make_float4(0.f,0.f,0.f,0.f);
    if (z0 > 0) plane(z0-1, sp, dum); else sp = z4;
    plane(z0, sc, cc_);
    for (int z = z0; z < z0 + ZL; z++) {
        if (z + 1 < D0) plane(z+1, sn, cn); else { sn = z4; cn = z4; }
        float4 o;
        float sx = sp.x + sc.x + sn.x;
        float sy = sp.y + sc.y + sn.y;
        float sz = sp.z + sc.z + sn.z;
        float sw_ = sp.w + sc.w + sn.w;
        o.x = (cc_.x == 0.f) ? sx  * (1.f/27.f) : cc_.x;
        o.y = (cc_.y == 0.f) ? sy  * (1.f/27.f) : cc_.y;
        o.z = (cc_.z == 0.f) ? sz  * (1.f/27.f) : cc_.z;
        o.w = (cc_.w == 0.f) ? sw_ * (1.f/27.f) : cc_.w;
        *(float4*)(outb + (size_t)z*HW0 + ro1) = o;
        sp = sc; sc = sn; cc_ = cn;
    }
}

// Fused downsample block, vectorized: conv(CIN->CC, k3 s2 p1) || maxpool(2^3),
// concat, relu. Each thread computes 4 consecutive x outputs; per input row a
// 9-value vector (2 float4 + 1 scalar) serves all 4 outputs' conv taps and the
// pool taps.
template<int CIN, int CC>
__global__ void k_down_v(const float* __restrict__ in, const float* __restrict__ w,
                         float* __restrict__ out,
                         int Dd, int Hh, int Ww, int Hin, int Win) {
    extern __shared__ float sw[];
    const int NW = CC*CIN*27;
    for (int i = threadIdx.x; i < NW; i += blockDim.x) sw[i] = w[i];
    __syncthreads();

    const int XQ = Ww/4;
    int N = Dd*Hh*Ww;
    int gid = blockIdx.x * blockDim.x + threadIdx.x;
    if (gid >= Dd*Hh*XQ) return;
    int xq = gid % XQ;
    int y  = (gid / XQ) % Hh;
    int z  = gid / (XQ*Hh);
    int x0 = xq * 4;
    size_t HWin = (size_t)Hin*Win;
    size_t Vin  = (size_t)(2*Dd)*HWin;

    float acc[CC][4];
    #pragma unroll
    for (int o = 0; o < CC; o++)
        #pragma unroll
        for (int i = 0; i < 4; i++) acc[o][i] = 0.f;

    bool lx = (x0 > 0);
    int outpos = (z*Hh + y)*Ww + x0;

    for (int ic = 0; ic < CIN; ic++) {
        const float* inp = in + (size_t)ic*Vin;
        float m[4] = {NEG_INF, NEG_INF, NEG_INF, NEG_INF};
        #pragma unroll
        for (int dz = 0; dz < 3; dz++) {
            int iz = 2*z - 1 + dz;
            if (iz < 0) continue;
            #pragma unroll
            for (int dy = 0; dy < 3; dy++) {
                int iy = 2*y - 1 + dy;
                if (iy < 0) continue;
                const float* r = inp + (size_t)iz*HWin + (size_t)iy*Win + 2*x0;
                float4 a = *(const float4*)r;
                float4 b = *(const float4*)(r + 4);
                float v0 = lx ? r[-1] : 0.f;   // zero-padding
                float v[9] = {v0, a.x, a.y, a.z, a.w, b.x, b.y, b.z, b.w};
                int wb = ic*27 + dz*9 + dy*3;
                #pragma unroll
                for (int o = 0; o < CC; o++) {
                    float w0 = sw[o*CIN*27 + wb + 0];
                    float w1 = sw[o*CIN*27 + wb + 1];
                    float w2 = sw[o*CIN*27 + wb + 2];
                    acc[o][0] = fmaf(w0, v[0], fmaf(w1, v[1], fmaf(w2, v[2], acc[o][0])));
                    acc[o][1] = fmaf(w0, v[2], fmaf(w1, v[3], fmaf(w2, v[4], acc[o][1])));
                    acc[o][2] = fmaf(w0, v[4], fmaf(w1, v[5], fmaf(w2, v[6], acc[o][2])));
                    acc[o][3] = fmaf(w0, v[6], fmaf(w1, v[7], fmaf(w2, v[8], acc[o][3])));
                }
                if (dz > 0 && dy > 0) {
                    #pragma unroll
                    for (int i = 0; i < 4; i++)
                        m[i] = fmaxf(m[i], fmaxf(v[2*i+1], v[2*i+2]));
                }
            }
        }
        float4 pm = make_float4(fmaxf(m[0],0.f), fmaxf(m[1],0.f),
                                fmaxf(m[2],0.f), fmaxf(m[3],0.f));
        *(float4*)(out + (size_t)(CC + ic)*N + outpos) = pm;
    }
    #pragma unroll
    for (int o = 0; o < CC; o++) {
        float4 co = make_float4(fmaxf(acc[o][0],0.f), fmaxf(acc[o][1],0.f),
                                fmaxf(acc[o][2],0.f), fmaxf(acc[o][3],0.f));
        *(float4*)(out + (size_t)o*N + outpos) = co;
    }
}

// Generic bottleneck conv: out = relu(conv(in) [+bias] [+add1] [+add2]).
// Weights OIDHW in smem, per-voxel thread.
template<int CIN, int COUT, int KD, int KH, int KW>
__global__ void k_conv(const float* __restrict__ in, const float* __restrict__ w,
                       const float* __restrict__ bias,
                       const float* __restrict__ add1, const float* __restrict__ add2,
                       float* __restrict__ out,
                       int Dd, int Hh, int Ww) {
    constexpr int KSZ = KD*KH*KW;
    __shared__ float sw[COUT*CIN*KSZ];
    __shared__ float sb[COUT];
    for (int i = threadIdx.x; i < COUT*CIN*KSZ; i += blockDim.x) sw[i] = w[i];
    if (threadIdx.x < COUT) sb[threadIdx.x] = bias ? bias[threadIdx.x] : 0.f;
    __syncthreads();

    int N = Dd*Hh*Ww;
    int gid = blockIdx.x * blockDim.x + threadIdx.x;
    if (gid >= N) return;
    int x = gid % Ww;
    int y = (gid / Ww) % Hh;
    int z = gid / (Ww*Hh);

    float acc[COUT];
    #pragma unroll
    for (int o = 0; o < COUT; o++) acc[o] = sb[o];

    for (int i = 0; i < CIN; i++) {
        const float* base = in + (size_t)i*N;
        #pragma unroll
        for (int dz = 0; dz < KD; dz++) {
            int iz = z - KD/2 + dz;
            if ((unsigned)iz >= (unsigned)Dd) continue;
            #pragma unroll
            for (int dy = 0; dy < KH; dy++) {
                int iy = y - KH/2 + dy;
                if ((unsigned)iy >= (unsigned)Hh) continue;
                #pragma unroll
                for (int dx = 0; dx < KW; dx++) {
                    int ix = x - KW/2 + dx;
                    if ((unsigned)ix >= (unsigned)Ww) continue;
                    float v = base[((size_t)iz*Hh + iy)*Ww + ix];
                    int widx = (i*KD + dz)*KH*KW + dy*KW + dx;
                    #pragma unroll
                    for (int o = 0; o < COUT; o++)
                        acc[o] = fmaf(sw[o*CIN*KSZ + widx], v, acc[o]);
                }
            }
        }
    }
    #pragma unroll
    for (int o = 0; o < COUT; o++) {
        float r = acc[o];
        if (add1) r += add1[(size_t)o*N + gid];
        if (add2) r += add2[(size_t)o*N + gid];
        out[(size_t)o*N + gid] = fmaxf(r, 0.f);
    }
}

// ---------------- launch ----------------
static inline int gridFor(long n, int b) { return (int)((n + b - 1) / b); }

extern "C" void kernel_launch(void* const* d_in, const int* in_sizes, int n_in,
                              void* d_out, int out_size) {
    const float* feat    = (const float*)d_in[0];
    const int*   depth   = (const int*)  d_in[1];
    const float* w_ds1   = (const float*)d_in[2];
    const float* b1_win  = (const float*)d_in[3];
    const float* b1_w133 = (const float*)d_in[4];
    const float* b1_b133 = (const float*)d_in[5];
    const float* b1_w331 = (const float*)d_in[6];
    const float* b1_b331 = (const float*)d_in[7];
    const float* b1_w313 = (const float*)d_in[8];
    const float* b1_b313 = (const float*)d_in[9];
    const float* b1_wout = (const float*)d_in[10];
    const float* w_ds2   = (const float*)d_in[11];
    const float* b2_win  = (const float*)d_in[12];
    const float* b2_w133 = (const float*)d_in[13];
    const float* b2_b133 = (const float*)d_in[14];
    const float* b2_w331 = (const float*)d_in[15];
    const float* b2_b331 = (const float*)d_in[16];
    const float* b2_w313 = (const float*)d_in[17];
    const float* b2_b313 = (const float*)d_in[18];
    const float* b2_wout = (const float*)d_in[19];
    float* out = (float*)d_out;

    void *p_filled_, *p_ds1_, *p_t0_, *p_t1_, *p_t2_, *p_t3_, *p_bn1_, *p_ds2_,
         *p_u0_, *p_u1_, *p_u2_, *p_u3_;
    cudaGetSymbolAddress(&p_filled_, g_filled);
    cudaGetSymbolAddress(&p_ds1_, g_ds1);
    cudaGetSymbolAddress(&p_t0_, g_t0);
    cudaGetSymbolAddress(&p_t1_, g_t1);
    cudaGetSymbolAddress(&p_t2_, g_t2);
    cudaGetSymbolAddress(&p_t3_, g_t3);
    cudaGetSymbolAddress(&p_bn1_, g_bn1);
    cudaGetSymbolAddress(&p_ds2_, g_ds2);
    cudaGetSymbolAddress(&p_u0_, g_u0);
    cudaGetSymbolAddress(&p_u1_, g_u1);
    cudaGetSymbolAddress(&p_u2_, g_u2);
    cudaGetSymbolAddress(&p_u3_, g_u3);
    float* p_filled = (float*)p_filled_;
    float* p_ds1 = (float*)p_ds1_;
    float* p_t0 = (float*)p_t0_; float* p_t1 = (float*)p_t1_;
    float* p_t2 = (float*)p_t2_; float* p_t3 = (float*)p_t3_;
    float* p_bn1 = (float*)p_bn1_;
    float* p_ds2 = (float*)p_ds2_;
    float* p_u0 = (float*)p_u0_; float* p_u1 = (float*)p_u1_;
    float* p_u2 = (float*)p_u2_; float* p_u3 = (float*)p_u3_;

    const int TB = 256;

    // scatter stage
    k_init   <<<gridFor((long)C0*VV/4, TB), TB>>>();
    k_winner <<<gridFor(PIX, TB), TB>>>(depth);
    k_scatter<<<gridFor(PIX, TB), TB>>>(feat, depth);

    // avgpool fill (vectorized, z-chunked)
    k_fill_v<<<gridFor((long)C0*H0*(W0/4)*ZCH, TB), TB>>>();

    // downsample 1: 12ch@240x144x240 -> 16ch@120x72x120
    k_down_v<12,4><<<gridFor((long)D1*H1*(W1/4), TB), TB, 4*12*27*sizeof(float)>>>(
        p_filled, w_ds1, p_ds1, D1, H1, W1, H0, W0);

    // bottleneck 1 (16 -> 4 -> ... -> 16, residual)
    k_conv<16,4,1,1,1><<<gridFor(N1, TB), TB>>>(p_ds1, b1_win,  nullptr, nullptr, nullptr, p_t0, D1, H1, W1);
    k_conv<4, 4,1,3,3><<<gridFor(N1, TB), TB>>>(p_t0,  b1_w133, b1_b133, nullptr, nullptr, p_t1, D1, H1, W1);
    k_conv<4, 4,3,3,1><<<gridFor(N1, TB), TB>>>(p_t1,  b1_w331, b1_b331, p_t1,    nullptr, p_t2, D1, H1, W1);
    k_conv<4, 4,3,1,3><<<gridFor(N1, TB), TB>>>(p_t2,  b1_w313, b1_b313, p_t2,    p_t1,    p_t3, D1, H1, W1);
    k_conv<4,16,1,1,1><<<gridFor(N1, TB), TB>>>(p_t3,  b1_wout, nullptr, p_ds1,   nullptr, p_bn1, D1, H1, W1);

    // downsample 2: 16ch@120x72x120 -> 32ch@60x36x60
    k_down_v<16,16><<<gridFor((long)D2*H2*(W2/4), TB), TB, 16*16*27*sizeof(float)>>>(
        p_bn1, w_ds2, p_ds2, D2, H2, W2, H1, W1);

    // bottleneck 2 (32 -> 8 -> ... -> 32, residual), final write to d_out
    k_conv<32,8,1,1,1><<<gridFor(N2, TB), TB>>>(p_ds2, b2_win,  nullptr, nullptr, nullptr, p_u0, D2, H2, W2);
    k_conv<8, 8,1,3,3><<<gridFor(N2, TB), TB>>>(p_u0,  b2_w133, b2_b133, nullptr, nullptr, p_u1, D2, H2, W2);
    k_conv<8, 8,3,3,1><<<gridFor(N2, TB), TB>>>(p_u1,  b2_w331, b2_b331, p_u1,    nullptr, p_u2, D2, H2, W2);
    k_conv<8, 8,3,1,3><<<gridFor(N2, TB), TB>>>(p_u2,  b2_w313, b2_b313, p_u2,    p_u1,    p_u3, D2, H2, W2);
    k_conv<8,32,1,1,1><<<gridFor(N2, TB), TB>>>(p_u3,  b2_wout, nullptr, p_ds2,   nullptr, out,  D2, H2, W2);
}